// round 16
// baseline (speedup 1.0000x reference)
#include <cuda_runtime.h>
#include <cuda_fp16.h>
#include <stdint.h>
#include <math.h>

// ---------------- problem constants ----------------
#define N_TOK 32768      // B*T = 4*8192
#define C_DIM 1024
#define HS    2048
#define HR    1024
#define NE    8

// Token permutation: physical row = (t & 7) * 4096 + (t >> 3)  (residue-major).

// ---------------- GEMM tile config (validated optimum) ----------------
#define BM 128
#define BN 128
#define BK 64
#define NSTG 3
#define ASTR (BK + 8)    // 72 halfs/row (144B, conflict-free ldmatrix)
#define BSTR (BN + 8)    // 136 halfs/row (272B, conflict-free ldmatrix.trans)
#define A_ST (BM * ASTR)             // 9216 halfs per A stage
#define B_ST (BK * BSTR)             // 8704 halfs per B stage
#define SMEM_BYTES (NSTG * (A_ST + B_ST) * 2)   // 107520 B -> 2 CTAs/SM

// fused grid layout
#define N_UP_SH   8192               // shared-up CTAs (bids 0..8191)
#define N_UP_RT   4096               // routed-up CTAs (bids 8192..12287)
#define N_UP      (N_UP_SH + N_UP_RT)
#define N_DOWN    2048               // down CTAs (bids 12288..14335)
#define N_TOTAL   (N_UP + N_DOWN)
#define READY_TARGET 1536            // producers per residue: 1024 shared + 512 routed

// ---------------- static scratch (no allocations allowed) ----------------
__device__ __half g_xh[N_TOK * C_DIM];          // x fp16, residue-major permuted
__device__ __half g_sw1h[C_DIM * HS];
__device__ __half g_sw3h[C_DIM * HS];
__device__ __half g_sw2h[HS * C_DIM];           // pre-scaled by 0.5
__device__ __half g_w1h[NE * C_DIM * HR];
__device__ __half g_w2h[NE * HR * C_DIM];       // pre-scaled by 0.25
__device__ __half g_H2[N_TOK * HS];             // swiglu hidden, permuted rows
__device__ __half g_Hr[2 * N_TOK * HR];         // routed hidden [k*8+r][4096][HR]
__device__ float  g_biasD[NE * C_DIM];          // combined down bias per residue
__device__ int    g_ready[NE];                  // per-residue producer counters

// ---------------- small PTX helpers ----------------
__device__ __forceinline__ void cp16(void* s, const void* g) {
    unsigned sa = (unsigned)__cvta_generic_to_shared(s);
    asm volatile("cp.async.cg.shared.global [%0], [%1], 16;" :: "r"(sa), "l"(g));
}
__device__ __forceinline__ void ldsm4(uint32_t* r, const __half* p) {
    unsigned a = (unsigned)__cvta_generic_to_shared(p);
    asm volatile("ldmatrix.sync.aligned.m8n8.x4.shared.b16 {%0,%1,%2,%3}, [%4];"
                 : "=r"(r[0]), "=r"(r[1]), "=r"(r[2]), "=r"(r[3]) : "r"(a));
}
__device__ __forceinline__ void ldsm4t(uint32_t* r, const __half* p) {
    unsigned a = (unsigned)__cvta_generic_to_shared(p);
    asm volatile("ldmatrix.sync.aligned.m8n8.x4.trans.shared.b16 {%0,%1,%2,%3}, [%4];"
                 : "=r"(r[0]), "=r"(r[1]), "=r"(r[2]), "=r"(r[3]) : "r"(a));
}
__device__ __forceinline__ void mma16816(float* d, const uint32_t* a, const uint32_t* b) {
    asm volatile(
        "mma.sync.aligned.m16n8k16.row.col.f32.f16.f16.f32 "
        "{%0,%1,%2,%3},{%4,%5,%6,%7},{%8,%9},{%0,%1,%2,%3};"
        : "+f"(d[0]), "+f"(d[1]), "+f"(d[2]), "+f"(d[3])
        : "r"(a[0]), "r"(a[1]), "r"(a[2]), "r"(a[3]), "r"(b[0]), "r"(b[1]));
}

// ---------------- merged conversion kernel (one launch, MLP x4) -----------
#define CV_NX ((N_TOK * C_DIM) / 4)     // 8388608
#define CV_NW ((C_DIM * HS) / 4)        // 524288
#define CV_NE ((NE * C_DIM * HR) / 4)   // 2097152
#define CV_TOTAL (CV_NX + 3 * CV_NW + 2 * CV_NE)   // 14155776
#define CV_QUARTER (CV_TOTAL / 4)                   // 3538944 (multiple of 256)

__device__ __forceinline__ void conv_one(
    int i,
    const float* __restrict__ x,
    const float* __restrict__ sw1, const float* __restrict__ sw3,
    const float* __restrict__ sw2,
    const float* __restrict__ w1,  const float* __restrict__ w2)
{
    if (i < CV_NX) {
        int t = i >> 8;                  // 256 float4 per row
        int c = i & 255;
        int pr = ((t & 7) << 12) | (t >> 3);
        float4 v = ((const float4*)x)[i];
        __half2* d = (__half2*)g_xh + (size_t)pr * (C_DIM / 2) + c * 2;
        d[0] = __floats2half2_rn(v.x, v.y);
        d[1] = __floats2half2_rn(v.z, v.w);
        return;
    }
    i -= CV_NX;
    const float* src; __half2* d; float sc;
    if (i < CV_NW)                  { src = sw1; d = (__half2*)g_sw1h; sc = 1.0f; }
    else if (i < 2 * CV_NW)         { src = sw3; d = (__half2*)g_sw3h; sc = 1.0f; i -= CV_NW; }
    else if (i < 3 * CV_NW)         { src = sw2; d = (__half2*)g_sw2h; sc = 0.5f; i -= 2 * CV_NW; }
    else if (i < 3 * CV_NW + CV_NE) { src = w1;  d = (__half2*)g_w1h;  sc = 1.0f; i -= 3 * CV_NW; }
    else                            { src = w2;  d = (__half2*)g_w2h;  sc = 0.25f; i -= 3 * CV_NW + CV_NE; }
    float4 v = ((const float4*)src)[i];
    d[2 * i]     = __floats2half2_rn(v.x * sc, v.y * sc);
    d[2 * i + 1] = __floats2half2_rn(v.z * sc, v.w * sc);
}

__global__ void k_convall(
    const float* __restrict__ x,
    const float* __restrict__ sw1, const float* __restrict__ sw3,
    const float* __restrict__ sw2,
    const float* __restrict__ w1,  const float* __restrict__ w2)
{
    int base = blockIdx.x * blockDim.x + threadIdx.x;   // [0, CV_QUARTER)
#pragma unroll
    for (int u = 0; u < 4; u++)
        conv_one(base + u * CV_QUARTER, x, sw1, sw3, sw2, w1, w2);
}

// combined down bias + per-call counter reset
__global__ void k_bias(const float* __restrict__ sb2, const float* __restrict__ b2) {
    int i = blockIdx.x * blockDim.x + threadIdx.x;
    if (i < NE) g_ready[i] = 0;
    if (i >= NE * C_DIM) return;
    int rr = i >> 10, col = i & 1023;
    int e0 = (3 * rr) & 7;
    int e1 = (3 * rr + 7) & 7;
    g_biasD[i] = 0.5f * sb2[col]
               + 0.25f * (b2[e0 * C_DIM + col] + b2[e1 * C_DIM + col]);
}

// ---------------- generic stage fill (BK=64, cp.async) ----------------
__device__ __forceinline__ void fill_stage(
    const __half* __restrict__ A, int strideA,
    const __half* __restrict__ B, int ldb,
    int m0, int n0, int kt, __half* Asb, __half* Bsb, int tid)
{
#pragma unroll
    for (int i = 0; i < 4; i++) {              // A: 128x64 halfs = 1024 x 16B chunks
        int c = tid + i * 256;
        int ar = c >> 3, ac = c & 7;
        cp16(Asb + ar * ASTR + ac * 8,
             A + (size_t)(m0 + ar) * strideA + kt * BK + ac * 8);
    }
#pragma unroll
    for (int i = 0; i < 4; i++) {              // B: 64x128 halfs = 1024 x 16B chunks
        int c = tid + i * 256;
        int br = c >> 4, bc = c & 15;
        cp16(Bsb + br * BSTR + bc * 8,
             B + (size_t)(kt * BK + br) * ldb + n0 + bc * 8);
    }
}

// ---------------- warp-tile compute on one resident stage (128x128, BK=64) ----------
__device__ __forceinline__ void compute_stage(
    const __half* As, const __half* Bs, float acc[2][8][4],
    int wm, int wn, int lane)
{
#pragma unroll
    for (int ks = 0; ks < 4; ks++) {           // four k16 steps per BK=64
        uint32_t a[2][4];
#pragma unroll
        for (int mi = 0; mi < 2; mi++) {
            const __half* p = &As[(wm * 32 + mi * 16 + (lane & 15)) * ASTR
                                  + ks * 16 + (lane >> 4) * 8];
            ldsm4(a[mi], p);
        }
#pragma unroll
        for (int p4 = 0; p4 < 4; p4++) {       // 16 cols per ldmatrix.x4.trans
            uint32_t b[4];
            const __half* p = &Bs[(ks * 16 + (lane & 7) + ((lane >> 3) & 1) * 8) * BSTR
                                  + wn * 64 + p4 * 16 + (lane >> 4) * 8];
            ldsm4t(b, p);
            mma16816(acc[0][2 * p4 + 0], a[0], &b[0]);
            mma16816(acc[0][2 * p4 + 1], a[0], &b[2]);
            mma16816(acc[1][2 * p4 + 0], a[1], &b[0]);
            mma16816(acc[1][2 * p4 + 1], a[1], &b[2]);
        }
    }
}

// ---------------- up-fused stage fill: A=x(perm), B=[sw1 64cols | sw3 64cols] -----
__device__ __forceinline__ void fill_stage_up(
    int kt, int m0, int n0, __half* Asb, __half* Bsb, int tid)
{
#pragma unroll
    for (int i = 0; i < 4; i++) {              // A: 128x64 halfs
        int c = tid + i * 256;
        int ar = c >> 3, ac = c & 7;
        cp16(Asb + ar * ASTR + ac * 8,
             g_xh + (size_t)(m0 + ar) * C_DIM + kt * BK + ac * 8);
    }
#pragma unroll
    for (int i = 0; i < 4; i++) {              // B: 64 rows x (64|64) halfs
        int c = tid + i * 256;
        int br = c >> 4, bc = c & 15;
        if (bc < 8)
            cp16(Bsb + br * BSTR + bc * 8,
                 g_sw1h + (size_t)(kt * BK + br) * HS + n0 + bc * 8);
        else
            cp16(Bsb + br * BSTR + 64 + (bc - 8) * 8,
                 g_sw3h + (size_t)(kt * BK + br) * HS + n0 + (bc - 8) * 8);
    }
}

// ---------------- down K-segment map (BK=64), contiguous A in permuted space ----
//   kt [0,32):  H2_perm[rr block] @ (0.5*sw2)
//   kt [32,48): Hr[rr]   @ (0.25*w2[e0])
//   kt [48,64): Hr[8+rr] @ (0.25*w2[e1])
#define KT_MEGA 64
__device__ __forceinline__ void mega_map(int kt, int rr, int e0, int e1,
                                         const __half*& Ap, int& sA, const __half*& Bp) {
    if (kt < 32) {
        Ap = g_H2 + (size_t)rr * 4096 * HS + (size_t)kt * BK;
        sA = HS;
        Bp = g_sw2h + (size_t)kt * BK * C_DIM;
    } else if (kt < 48) {
        Ap = g_Hr + (size_t)rr * 4096 * HR + (size_t)(kt - 32) * BK;
        sA = HR;
        Bp = g_w2h + (size_t)e0 * HR * C_DIM + (size_t)(kt - 32) * BK * C_DIM;
    } else {
        Ap = g_Hr + (size_t)(8 + rr) * 4096 * HR + (size_t)(kt - 48) * BK;
        sA = HR;
        Bp = g_w2h + (size_t)e1 * HR * C_DIM + (size_t)(kt - 48) * BK * C_DIM;
    }
}
__device__ __forceinline__ void fill_stage_mega(
    int kt, int rr, int e0, int e1, int m0, int n0,
    __half* Asb, __half* Bsb, int tid)
{
    const __half* Ap; const __half* Bp; int sA;
    mega_map(kt, rr, e0, e1, Ap, sA, Bp);
#pragma unroll
    for (int i = 0; i < 4; i++) {
        int c = tid + i * 256;
        int ar = c >> 3, ac = c & 7;
        cp16(Asb + ar * ASTR + ac * 8,
             Ap + (size_t)(m0 + ar) * sA + ac * 8);
    }
#pragma unroll
    for (int i = 0; i < 4; i++) {
        int c = tid + i * 256;
        int br = c >> 4, bc = c & 15;
        cp16(Bsb + br * BSTR + bc * 8,
             Bp + (size_t)br * C_DIM + n0 + bc * 8);
    }
}

// producer signal: release-fence then count up for residue rr (one thread)
__device__ __forceinline__ void signal_ready(int rr, int tid) {
    __syncthreads();                 // all stores in CTA done
    if (tid == 0) {
        __threadfence();             // release
        atomicAdd(&g_ready[rr], 1);
    }
}

// ================= FUSED kernel: up (producers) + down (consumers) ============
// 1D grid, 14336 CTAs, bid-ordered so all producers dispatch before consumers:
//   [0, 8192)      shared-up  (residue rr = bid>>10; 1024 CTAs per rr)
//   [8192, 12288)  routed-up  (z = rid>>8, rr = z&7; 512 CTAs per rr)
//   [12288, 14336) down       (rr = idx>>8 ascending; waits g_ready[rr]==1536)
__global__ __launch_bounds__(256, 2) void k_fused(
    const float* __restrict__ sb1, const float* __restrict__ sb3,
    const float* __restrict__ b1, float* __restrict__ dout)
{
    extern __shared__ __align__(16) __half smem[];
    __half* Asm = smem;
    __half* Bsm = smem + NSTG * A_ST;

    const int tid = threadIdx.x;
    const int bid = blockIdx.x;
    const int warp = tid >> 5, lane = tid & 31;

    if (bid < N_UP_SH) {
        // ---------- shared up: H2 = silu(x@sw1+b1)*(x@sw3+b3) ----------
        const int KT = C_DIM / BK;             // 16
        const int m0 = (bid >> 5) * BM;
        const int n0 = (bid & 31) * 64;
        const int wm = warp & 3, wn = (warp >> 2) & 1;

#pragma unroll
        for (int c = 0; c < NSTG - 1; c++) {
            fill_stage_up(c, m0, n0, Asm + c * A_ST, Bsm + c * B_ST, tid);
            asm volatile("cp.async.commit_group;");
        }

        float acc1[2][4][4], acc3[2][4][4];
#pragma unroll
        for (int i = 0; i < 2; i++)
#pragma unroll
            for (int j = 0; j < 4; j++)
#pragma unroll
                for (int e = 0; e < 4; e++) { acc1[i][j][e] = 0.f; acc3[i][j][e] = 0.f; }

        int s = 0, fs = NSTG - 1;
        for (int kt = 0; kt < KT; ++kt) {
            asm volatile("cp.async.wait_group %0;" :: "n"(NSTG - 2));
            __syncthreads();

            const __half* As = Asm + s * A_ST;
            const __half* Bs = Bsm + s * B_ST;
#pragma unroll
            for (int ks = 0; ks < 4; ks++) {
                uint32_t a[2][4];
#pragma unroll
                for (int mi = 0; mi < 2; mi++) {
                    const __half* p = &As[(wm * 32 + mi * 16 + (lane & 15)) * ASTR
                                          + ks * 16 + (lane >> 4) * 8];
                    ldsm4(a[mi], p);
                }
                const int brow = (ks * 16 + (lane & 7) + ((lane >> 3) & 1) * 8) * BSTR
                                 + (lane >> 4) * 8;
#pragma unroll
                for (int p4 = 0; p4 < 2; p4++) {   // branch 1 (sw1)
                    uint32_t b[4];
                    ldsm4t(b, &Bs[brow + wn * 32 + p4 * 16]);
                    mma16816(acc1[0][2 * p4 + 0], a[0], &b[0]);
                    mma16816(acc1[0][2 * p4 + 1], a[0], &b[2]);
                    mma16816(acc1[1][2 * p4 + 0], a[1], &b[0]);
                    mma16816(acc1[1][2 * p4 + 1], a[1], &b[2]);
                }
#pragma unroll
                for (int p4 = 0; p4 < 2; p4++) {   // branch 3 (sw3): +64 col offset
                    uint32_t b[4];
                    ldsm4t(b, &Bs[brow + 64 + wn * 32 + p4 * 16]);
                    mma16816(acc3[0][2 * p4 + 0], a[0], &b[0]);
                    mma16816(acc3[0][2 * p4 + 1], a[0], &b[2]);
                    mma16816(acc3[1][2 * p4 + 0], a[1], &b[0]);
                    mma16816(acc3[1][2 * p4 + 1], a[1], &b[2]);
                }
            }

            if (kt + NSTG - 1 < KT)
                fill_stage_up(kt + NSTG - 1, m0, n0,
                              Asm + fs * A_ST, Bsm + fs * B_ST, tid);
            asm volatile("cp.async.commit_group;");

            if (++s == NSTG) s = 0;
            if (++fs == NSTG) fs = 0;
        }

#pragma unroll
        for (int mi = 0; mi < 2; mi++)
#pragma unroll
            for (int ni = 0; ni < 4; ni++)
#pragma unroll
                for (int pp = 0; pp < 2; pp++) {
                    int row = m0 + wm * 32 + mi * 16 + (lane >> 2) + pp * 8;
                    int col = n0 + wn * 32 + ni * 8 + (lane & 3) * 2;
                    float u0 = acc1[mi][ni][2 * pp + 0] + sb1[col];
                    float u1 = acc1[mi][ni][2 * pp + 1] + sb1[col + 1];
                    float w0 = acc3[mi][ni][2 * pp + 0] + sb3[col];
                    float w1 = acc3[mi][ni][2 * pp + 1] + sb3[col + 1];
                    float v0 = u0 / (1.f + __expf(-u0)) * w0;
                    float v1 = u1 / (1.f + __expf(-u1)) * w1;
                    *(__half2*)(g_H2 + (size_t)row * HS + col) = __floats2half2_rn(v0, v1);
                }

        signal_ready(bid >> 10, tid);
    } else if (bid < N_UP) {
        // ---------- routed up: Hr[z] = gelu(x_perm[rr block] @ w1[e] + b1[e]) ------
        const int KT = C_DIM / BK;
        const int rid = bid - N_UP_SH;
        const int z = rid >> 8;               // 0..15, z = kk*8 + rr
        const int rr = z & 7, kk = z >> 3;
        const int e = (3 * rr + 7 * kk) & 7;
        const int m0 = ((rid >> 3) & 31) * BM;
        const int n0 = (rid & 7) * BN;
        const __half* A = g_xh + (size_t)rr * 4096 * C_DIM;   // contiguous rows
        const __half* B = g_w1h + (size_t)e * C_DIM * HR;
        __half* outp = g_Hr + (size_t)z * 4096 * HR;
        const float* bias = b1 + e * HR;
        const int wm = warp & 3, wn = warp >> 2;

#pragma unroll
        for (int c = 0; c < NSTG - 1; c++) {
            fill_stage(A, C_DIM, B, HR, m0, n0, c,
                       Asm + c * A_ST, Bsm + c * B_ST, tid);
            asm volatile("cp.async.commit_group;");
        }

        float acc[2][8][4];
#pragma unroll
        for (int i = 0; i < 2; i++)
#pragma unroll
            for (int j = 0; j < 8; j++)
#pragma unroll
                for (int ee = 0; ee < 4; ee++) acc[i][j][ee] = 0.f;

        int s = 0, fs = NSTG - 1;
        for (int kt = 0; kt < KT; ++kt) {
            asm volatile("cp.async.wait_group %0;" :: "n"(NSTG - 2));
            __syncthreads();

            compute_stage(Asm + s * A_ST, Bsm + s * B_ST, acc, wm, wn, lane);

            if (kt + NSTG - 1 < KT)
                fill_stage(A, C_DIM, B, HR, m0, n0, kt + NSTG - 1,
                           Asm + fs * A_ST, Bsm + fs * B_ST, tid);
            asm volatile("cp.async.commit_group;");

            if (++s == NSTG) s = 0;
            if (++fs == NSTG) fs = 0;
        }

#pragma unroll
        for (int mi = 0; mi < 2; mi++)
#pragma unroll
            for (int ni = 0; ni < 8; ni++)
#pragma unroll
                for (int pp = 0; pp < 2; pp++) {
                    int row = m0 + wm * 32 + mi * 16 + (lane >> 2) + pp * 8;
                    int col = n0 + wn * 64 + ni * 8 + (lane & 3) * 2;
                    float v0 = acc[mi][ni][2 * pp + 0] + bias[col];
                    float v1 = acc[mi][ni][2 * pp + 1] + bias[col + 1];
                    v0 = 0.5f * v0 * (1.f + erff(v0 * 0.70710678118654752f));
                    v1 = 0.5f * v1 * (1.f + erff(v1 * 0.70710678118654752f));
                    *(__half2*)(outp + (size_t)row * HR + col) = __floats2half2_rn(v0, v1);
                }

        signal_ready(rr, tid);
    } else {
        // ---------- down: out = 0.5*shared_down + 0.25*(y0+y1) ----------
        const int idx = bid - N_UP;
        const int rr = idx >> 8;              // ascending: rr=0 CTAs dispatch first
        const int rem = idx & 255;
        const int m0 = (rem >> 3) * BM;
        const int n0 = (rem & 7) * BN;
        const int e0 = (3 * rr) & 7;
        const int e1 = (3 * rr + 7) & 7;
        const int wm = warp & 3, wn = warp >> 2;

        // wait until all producers for this residue have committed
        if (tid == 0) {
            while (atomicAdd(&g_ready[rr], 0) < READY_TARGET) __nanosleep(200);
        }
        __syncthreads();
        __threadfence();                     // acquire side

#pragma unroll
        for (int c = 0; c < NSTG - 1; c++) {
            fill_stage_mega(c, rr, e0, e1, m0, n0,
                            Asm + c * A_ST, Bsm + c * B_ST, tid);
            asm volatile("cp.async.commit_group;");
        }

        float acc[2][8][4];
#pragma unroll
        for (int i = 0; i < 2; i++)
#pragma unroll
            for (int j = 0; j < 8; j++)
#pragma unroll
                for (int e = 0; e < 4; e++) acc[i][j][e] = 0.f;

        int s = 0, fs = NSTG - 1;
        for (int kt = 0; kt < KT_MEGA; ++kt) {
            asm volatile("cp.async.wait_group %0;" :: "n"(NSTG - 2));
            __syncthreads();

            compute_stage(Asm + s * A_ST, Bsm + s * B_ST, acc, wm, wn, lane);

            if (kt + NSTG - 1 < KT_MEGA)
                fill_stage_mega(kt + NSTG - 1, rr, e0, e1, m0, n0,
                                Asm + fs * A_ST, Bsm + fs * B_ST, tid);
            asm volatile("cp.async.commit_group;");

            if (++s == NSTG) s = 0;
            if (++fs == NSTG) fs = 0;
        }

        // epilogue: single fp32 write, precomputed combined bias, un-permute rows
        const float* biasD = g_biasD + rr * C_DIM;
#pragma unroll
        for (int mi = 0; mi < 2; mi++)
#pragma unroll
            for (int ni = 0; ni < 8; ni++)
#pragma unroll
                for (int pp = 0; pp < 2; pp++) {
                    int rowl = m0 + wm * 32 + mi * 16 + (lane >> 2) + pp * 8;
                    int col  = n0 + wn * 64 + ni * 8 + (lane & 3) * 2;
                    float2 bb = *(const float2*)(biasD + col);
                    float2 f;
                    f.x = acc[mi][ni][2 * pp + 0] + bb.x;
                    f.y = acc[mi][ni][2 * pp + 1] + bb.y;
                    size_t t = (size_t)rr + 8 * (size_t)rowl;    // actual token
                    *(float2*)(dout + t * C_DIM + col) = f;
                }
    }
}

// ---------------- launch ----------------
extern "C" void kernel_launch(void* const* d_in, const int* in_sizes, int n_in,
                              void* d_out, int out_size) {
    const float* x   = (const float*)d_in[0];
    // d_in[1] = t_emb : unused by reference
    const float* sw1 = (const float*)d_in[2];
    const float* sb1 = (const float*)d_in[3];
    const float* sw3 = (const float*)d_in[4];
    const float* sb3 = (const float*)d_in[5];
    const float* sw2 = (const float*)d_in[6];
    const float* sb2 = (const float*)d_in[7];
    const float* w1  = (const float*)d_in[8];
    const float* b1  = (const float*)d_in[9];
    const float* w2  = (const float*)d_in[10];
    const float* b2  = (const float*)d_in[11];
    float* out = (float*)d_out;

    cudaFuncSetAttribute(k_fused, cudaFuncAttributeMaxDynamicSharedMemorySize, SMEM_BYTES);

    // one merged conversion launch (MLP x4) + bias/counter-reset kernel
    k_convall<<<CV_QUARTER / 256, 256>>>(x, sw1, sw3, sw2, w1, w2);
    k_bias<<<(NE * C_DIM + 255) / 256, 256>>>(sb2, b2);

    // fused up+down: producers signal per-residue counters, consumers spin-wait
    k_fused<<<N_TOTAL, 256, SMEM_BYTES>>>(sb1, sb3, b1, out);
}

// round 17
// speedup vs baseline: 1.0065x; 1.0065x over previous
#include <cuda_runtime.h>
#include <cuda_fp16.h>
#include <stdint.h>
#include <math.h>

// ---------------- problem constants ----------------
#define N_TOK 32768      // B*T = 4*8192
#define C_DIM 1024
#define HS    2048
#define HR    1024
#define NE    8

// Token permutation: physical row = (t & 7) * 4096 + (t >> 3)  (residue-major).

// ---------------- GEMM tile config (validated optimum) ----------------
#define BM 128
#define BN 128
#define BK 64
#define NSTG 3
#define ASTR (BK + 8)    // 72 halfs/row (144B, conflict-free ldmatrix)
#define BSTR (BN + 8)    // 136 halfs/row (272B, conflict-free ldmatrix.trans)
#define A_ST (BM * ASTR)             // 9216 halfs per A stage
#define B_ST (BK * BSTR)             // 8704 halfs per B stage
#define SMEM_BYTES (NSTG * (A_ST + B_ST) * 2)   // 107520 B -> 2 CTAs/SM

// fused grid layout: producers residue-major, then consumers
#define PROD_PER_RR 1536             // 1024 shared-up + 512 routed-up per residue
#define N_UP      (NE * PROD_PER_RR) // 12288
#define N_DOWN    2048               // down CTAs (bids 12288..14335)
#define N_TOTAL   (N_UP + N_DOWN)
#define READY_TARGET PROD_PER_RR

// ---------------- static scratch (no allocations allowed) ----------------
__device__ __half g_xh[N_TOK * C_DIM];          // x fp16, residue-major permuted
__device__ __half g_sw1h[C_DIM * HS];
__device__ __half g_sw3h[C_DIM * HS];
__device__ __half g_sw2h[HS * C_DIM];           // pre-scaled by 0.5
__device__ __half g_w1h[NE * C_DIM * HR];
__device__ __half g_w2h[NE * HR * C_DIM];       // pre-scaled by 0.25
__device__ __half g_H2[N_TOK * HS];             // swiglu hidden, permuted rows
__device__ __half g_Hr[2 * N_TOK * HR];         // routed hidden [k*8+r][4096][HR]
__device__ float  g_biasD[NE * C_DIM];          // combined down bias per residue
__device__ int    g_ready[NE];                  // per-residue producer counters

// ---------------- small PTX helpers ----------------
__device__ __forceinline__ void cp16(void* s, const void* g) {
    unsigned sa = (unsigned)__cvta_generic_to_shared(s);
    asm volatile("cp.async.cg.shared.global [%0], [%1], 16;" :: "r"(sa), "l"(g));
}
__device__ __forceinline__ void ldsm4(uint32_t* r, const __half* p) {
    unsigned a = (unsigned)__cvta_generic_to_shared(p);
    asm volatile("ldmatrix.sync.aligned.m8n8.x4.shared.b16 {%0,%1,%2,%3}, [%4];"
                 : "=r"(r[0]), "=r"(r[1]), "=r"(r[2]), "=r"(r[3]) : "r"(a));
}
__device__ __forceinline__ void ldsm4t(uint32_t* r, const __half* p) {
    unsigned a = (unsigned)__cvta_generic_to_shared(p);
    asm volatile("ldmatrix.sync.aligned.m8n8.x4.trans.shared.b16 {%0,%1,%2,%3}, [%4];"
                 : "=r"(r[0]), "=r"(r[1]), "=r"(r[2]), "=r"(r[3]) : "r"(a));
}
__device__ __forceinline__ void mma16816(float* d, const uint32_t* a, const uint32_t* b) {
    asm volatile(
        "mma.sync.aligned.m16n8k16.row.col.f32.f16.f16.f32 "
        "{%0,%1,%2,%3},{%4,%5,%6,%7},{%8,%9},{%0,%1,%2,%3};"
        : "+f"(d[0]), "+f"(d[1]), "+f"(d[2]), "+f"(d[3])
        : "r"(a[0]), "r"(a[1]), "r"(a[2]), "r"(a[3]), "r"(b[0]), "r"(b[1]));
}

// ---------------- merged conversion kernel (one launch, MLP x4) -----------
#define CV_NX ((N_TOK * C_DIM) / 4)     // 8388608
#define CV_NW ((C_DIM * HS) / 4)        // 524288
#define CV_NE ((NE * C_DIM * HR) / 4)   // 2097152
#define CV_TOTAL (CV_NX + 3 * CV_NW + 2 * CV_NE)   // 14155776
#define CV_QUARTER (CV_TOTAL / 4)                   // 3538944 (multiple of 256)

__device__ __forceinline__ void conv_one(
    int i,
    const float* __restrict__ x,
    const float* __restrict__ sw1, const float* __restrict__ sw3,
    const float* __restrict__ sw2,
    const float* __restrict__ w1,  const float* __restrict__ w2)
{
    if (i < CV_NX) {
        int t = i >> 8;                  // 256 float4 per row
        int c = i & 255;
        int pr = ((t & 7) << 12) | (t >> 3);
        float4 v = ((const float4*)x)[i];
        __half2* d = (__half2*)g_xh + (size_t)pr * (C_DIM / 2) + c * 2;
        d[0] = __floats2half2_rn(v.x, v.y);
        d[1] = __floats2half2_rn(v.z, v.w);
        return;
    }
    i -= CV_NX;
    const float* src; __half2* d; float sc;
    if (i < CV_NW)                  { src = sw1; d = (__half2*)g_sw1h; sc = 1.0f; }
    else if (i < 2 * CV_NW)         { src = sw3; d = (__half2*)g_sw3h; sc = 1.0f; i -= CV_NW; }
    else if (i < 3 * CV_NW)         { src = sw2; d = (__half2*)g_sw2h; sc = 0.5f; i -= 2 * CV_NW; }
    else if (i < 3 * CV_NW + CV_NE) { src = w1;  d = (__half2*)g_w1h;  sc = 1.0f; i -= 3 * CV_NW; }
    else                            { src = w2;  d = (__half2*)g_w2h;  sc = 0.25f; i -= 3 * CV_NW + CV_NE; }
    float4 v = ((const float4*)src)[i];
    d[2 * i]     = __floats2half2_rn(v.x * sc, v.y * sc);
    d[2 * i + 1] = __floats2half2_rn(v.z * sc, v.w * sc);
}

__global__ void k_convall(
    const float* __restrict__ x,
    const float* __restrict__ sw1, const float* __restrict__ sw3,
    const float* __restrict__ sw2,
    const float* __restrict__ w1,  const float* __restrict__ w2)
{
    int base = blockIdx.x * blockDim.x + threadIdx.x;   // [0, CV_QUARTER)
#pragma unroll
    for (int u = 0; u < 4; u++)
        conv_one(base + u * CV_QUARTER, x, sw1, sw3, sw2, w1, w2);
}

// combined down bias + per-call counter reset
__global__ void k_bias(const float* __restrict__ sb2, const float* __restrict__ b2) {
    int i = blockIdx.x * blockDim.x + threadIdx.x;
    if (i < NE) g_ready[i] = 0;
    if (i >= NE * C_DIM) return;
    int rr = i >> 10, col = i & 1023;
    int e0 = (3 * rr) & 7;
    int e1 = (3 * rr + 7) & 7;
    g_biasD[i] = 0.5f * sb2[col]
               + 0.25f * (b2[e0 * C_DIM + col] + b2[e1 * C_DIM + col]);
}

// ---------------- generic stage fill (BK=64, cp.async) ----------------
__device__ __forceinline__ void fill_stage(
    const __half* __restrict__ A, int strideA,
    const __half* __restrict__ B, int ldb,
    int m0, int n0, int kt, __half* Asb, __half* Bsb, int tid)
{
#pragma unroll
    for (int i = 0; i < 4; i++) {              // A: 128x64 halfs = 1024 x 16B chunks
        int c = tid + i * 256;
        int ar = c >> 3, ac = c & 7;
        cp16(Asb + ar * ASTR + ac * 8,
             A + (size_t)(m0 + ar) * strideA + kt * BK + ac * 8);
    }
#pragma unroll
    for (int i = 0; i < 4; i++) {              // B: 64x128 halfs = 1024 x 16B chunks
        int c = tid + i * 256;
        int br = c >> 4, bc = c & 15;
        cp16(Bsb + br * BSTR + bc * 8,
             B + (size_t)(kt * BK + br) * ldb + n0 + bc * 8);
    }
}

// ---------------- warp-tile compute on one resident stage (128x128, BK=64) ----------
__device__ __forceinline__ void compute_stage(
    const __half* As, const __half* Bs, float acc[2][8][4],
    int wm, int wn, int lane)
{
#pragma unroll
    for (int ks = 0; ks < 4; ks++) {           // four k16 steps per BK=64
        uint32_t a[2][4];
#pragma unroll
        for (int mi = 0; mi < 2; mi++) {
            const __half* p = &As[(wm * 32 + mi * 16 + (lane & 15)) * ASTR
                                  + ks * 16 + (lane >> 4) * 8];
            ldsm4(a[mi], p);
        }
#pragma unroll
        for (int p4 = 0; p4 < 4; p4++) {       // 16 cols per ldmatrix.x4.trans
            uint32_t b[4];
            const __half* p = &Bs[(ks * 16 + (lane & 7) + ((lane >> 3) & 1) * 8) * BSTR
                                  + wn * 64 + p4 * 16 + (lane >> 4) * 8];
            ldsm4t(b, p);
            mma16816(acc[0][2 * p4 + 0], a[0], &b[0]);
            mma16816(acc[0][2 * p4 + 1], a[0], &b[2]);
            mma16816(acc[1][2 * p4 + 0], a[1], &b[0]);
            mma16816(acc[1][2 * p4 + 1], a[1], &b[2]);
        }
    }
}

// ---------------- up-fused stage fill: A=x(perm), B=[sw1 64cols | sw3 64cols] -----
__device__ __forceinline__ void fill_stage_up(
    int kt, int m0, int n0, __half* Asb, __half* Bsb, int tid)
{
#pragma unroll
    for (int i = 0; i < 4; i++) {              // A: 128x64 halfs
        int c = tid + i * 256;
        int ar = c >> 3, ac = c & 7;
        cp16(Asb + ar * ASTR + ac * 8,
             g_xh + (size_t)(m0 + ar) * C_DIM + kt * BK + ac * 8);
    }
#pragma unroll
    for (int i = 0; i < 4; i++) {              // B: 64 rows x (64|64) halfs
        int c = tid + i * 256;
        int br = c >> 4, bc = c & 15;
        if (bc < 8)
            cp16(Bsb + br * BSTR + bc * 8,
                 g_sw1h + (size_t)(kt * BK + br) * HS + n0 + bc * 8);
        else
            cp16(Bsb + br * BSTR + 64 + (bc - 8) * 8,
                 g_sw3h + (size_t)(kt * BK + br) * HS + n0 + (bc - 8) * 8);
    }
}

// ---------------- down K-segment map (BK=64), contiguous A in permuted space ----
//   kt [0,32):  H2_perm[rr block] @ (0.5*sw2)
//   kt [32,48): Hr[rr]   @ (0.25*w2[e0])
//   kt [48,64): Hr[8+rr] @ (0.25*w2[e1])
#define KT_MEGA 64
__device__ __forceinline__ void mega_map(int kt, int rr, int e0, int e1,
                                         const __half*& Ap, int& sA, const __half*& Bp) {
    if (kt < 32) {
        Ap = g_H2 + (size_t)rr * 4096 * HS + (size_t)kt * BK;
        sA = HS;
        Bp = g_sw2h + (size_t)kt * BK * C_DIM;
    } else if (kt < 48) {
        Ap = g_Hr + (size_t)rr * 4096 * HR + (size_t)(kt - 32) * BK;
        sA = HR;
        Bp = g_w2h + (size_t)e0 * HR * C_DIM + (size_t)(kt - 32) * BK * C_DIM;
    } else {
        Ap = g_Hr + (size_t)(8 + rr) * 4096 * HR + (size_t)(kt - 48) * BK;
        sA = HR;
        Bp = g_w2h + (size_t)e1 * HR * C_DIM + (size_t)(kt - 48) * BK * C_DIM;
    }
}
__device__ __forceinline__ void fill_stage_mega(
    int kt, int rr, int e0, int e1, int m0, int n0,
    __half* Asb, __half* Bsb, int tid)
{
    const __half* Ap; const __half* Bp; int sA;
    mega_map(kt, rr, e0, e1, Ap, sA, Bp);
#pragma unroll
    for (int i = 0; i < 4; i++) {
        int c = tid + i * 256;
        int ar = c >> 3, ac = c & 7;
        cp16(Asb + ar * ASTR + ac * 8,
             Ap + (size_t)(m0 + ar) * sA + ac * 8);
    }
#pragma unroll
    for (int i = 0; i < 4; i++) {
        int c = tid + i * 256;
        int br = c >> 4, bc = c & 15;
        cp16(Bsb + br * BSTR + bc * 8,
             Bp + (size_t)br * C_DIM + n0 + bc * 8);
    }
}

// producer signal: release-fence then count up for residue rr (one thread)
__device__ __forceinline__ void signal_ready(int rr, int tid) {
    __syncthreads();                 // all stores in CTA done
    if (tid == 0) {
        __threadfence();             // release
        atomicAdd(&g_ready[rr], 1);
    }
}

// ================= FUSED kernel: up (producers, residue-major) + down =========
// 1D grid, 14336 CTAs, bid-ordered:
//   [0, 12288): producers; rr = bid/1536, local = bid%1536
//               local < 1024  -> shared-up tile within rr's row block
//               local >= 1024 -> routed-up (kk = (local-1024)>>8, z = kk*8+rr)
//   [12288, 14336): down; rr = idx>>8; waits g_ready[rr]==1536
__global__ __launch_bounds__(256, 2) void k_fused(
    const float* __restrict__ sb1, const float* __restrict__ sb3,
    const float* __restrict__ b1, float* __restrict__ dout)
{
    extern __shared__ __align__(16) __half smem[];
    __half* Asm = smem;
    __half* Bsm = smem + NSTG * A_ST;

    const int tid = threadIdx.x;
    const int bid = blockIdx.x;
    const int warp = tid >> 5, lane = tid & 31;

    if (bid < N_UP) {
        const int rr = bid / PROD_PER_RR;
        const int local = bid - rr * PROD_PER_RR;
        const int KT = C_DIM / BK;             // 16

        if (local < 1024) {
            // ---------- shared up: H2 = silu(x@sw1+b1)*(x@sw3+b3) ----------
            const int m0 = rr * 4096 + (local >> 5) * BM;
            const int n0 = (local & 31) * 64;
            const int wm = warp & 3, wn = (warp >> 2) & 1;

#pragma unroll
            for (int c = 0; c < NSTG - 1; c++) {
                fill_stage_up(c, m0, n0, Asm + c * A_ST, Bsm + c * B_ST, tid);
                asm volatile("cp.async.commit_group;");
            }

            float acc1[2][4][4], acc3[2][4][4];
#pragma unroll
            for (int i = 0; i < 2; i++)
#pragma unroll
                for (int j = 0; j < 4; j++)
#pragma unroll
                    for (int e = 0; e < 4; e++) { acc1[i][j][e] = 0.f; acc3[i][j][e] = 0.f; }

            int s = 0, fs = NSTG - 1;
            for (int kt = 0; kt < KT; ++kt) {
                asm volatile("cp.async.wait_group %0;" :: "n"(NSTG - 2));
                __syncthreads();

                const __half* As = Asm + s * A_ST;
                const __half* Bs = Bsm + s * B_ST;
#pragma unroll
                for (int ks = 0; ks < 4; ks++) {
                    uint32_t a[2][4];
#pragma unroll
                    for (int mi = 0; mi < 2; mi++) {
                        const __half* p = &As[(wm * 32 + mi * 16 + (lane & 15)) * ASTR
                                              + ks * 16 + (lane >> 4) * 8];
                        ldsm4(a[mi], p);
                    }
                    const int brow = (ks * 16 + (lane & 7) + ((lane >> 3) & 1) * 8) * BSTR
                                     + (lane >> 4) * 8;
#pragma unroll
                    for (int p4 = 0; p4 < 2; p4++) {   // branch 1 (sw1)
                        uint32_t b[4];
                        ldsm4t(b, &Bs[brow + wn * 32 + p4 * 16]);
                        mma16816(acc1[0][2 * p4 + 0], a[0], &b[0]);
                        mma16816(acc1[0][2 * p4 + 1], a[0], &b[2]);
                        mma16816(acc1[1][2 * p4 + 0], a[1], &b[0]);
                        mma16816(acc1[1][2 * p4 + 1], a[1], &b[2]);
                    }
#pragma unroll
                    for (int p4 = 0; p4 < 2; p4++) {   // branch 3 (sw3): +64 col offset
                        uint32_t b[4];
                        ldsm4t(b, &Bs[brow + 64 + wn * 32 + p4 * 16]);
                        mma16816(acc3[0][2 * p4 + 0], a[0], &b[0]);
                        mma16816(acc3[0][2 * p4 + 1], a[0], &b[2]);
                        mma16816(acc3[1][2 * p4 + 0], a[1], &b[0]);
                        mma16816(acc3[1][2 * p4 + 1], a[1], &b[2]);
                    }
                }

                if (kt + NSTG - 1 < KT)
                    fill_stage_up(kt + NSTG - 1, m0, n0,
                                  Asm + fs * A_ST, Bsm + fs * B_ST, tid);
                asm volatile("cp.async.commit_group;");

                if (++s == NSTG) s = 0;
                if (++fs == NSTG) fs = 0;
            }

#pragma unroll
            for (int mi = 0; mi < 2; mi++)
#pragma unroll
                for (int ni = 0; ni < 4; ni++)
#pragma unroll
                    for (int pp = 0; pp < 2; pp++) {
                        int row = m0 + wm * 32 + mi * 16 + (lane >> 2) + pp * 8;
                        int col = n0 + wn * 32 + ni * 8 + (lane & 3) * 2;
                        float u0 = acc1[mi][ni][2 * pp + 0] + sb1[col];
                        float u1 = acc1[mi][ni][2 * pp + 1] + sb1[col + 1];
                        float w0 = acc3[mi][ni][2 * pp + 0] + sb3[col];
                        float w1 = acc3[mi][ni][2 * pp + 1] + sb3[col + 1];
                        float v0 = u0 / (1.f + __expf(-u0)) * w0;
                        float v1 = u1 / (1.f + __expf(-u1)) * w1;
                        *(__half2*)(g_H2 + (size_t)row * HS + col) = __floats2half2_rn(v0, v1);
                    }
        } else {
            // ---------- routed up: Hr[z] = gelu(x_perm[rr block] @ w1[e] + b1[e]) ---
            const int rid = local - 1024;         // 0..511
            const int kk = rid >> 8;
            const int z = kk * 8 + rr;
            const int e = (3 * rr + 7 * kk) & 7;
            const int m0 = ((rid >> 3) & 31) * BM;
            const int n0 = (rid & 7) * BN;
            const __half* A = g_xh + (size_t)rr * 4096 * C_DIM;   // contiguous rows
            const __half* B = g_w1h + (size_t)e * C_DIM * HR;
            __half* outp = g_Hr + (size_t)z * 4096 * HR;
            const float* bias = b1 + e * HR;
            const int wm = warp & 3, wn = warp >> 2;

#pragma unroll
            for (int c = 0; c < NSTG - 1; c++) {
                fill_stage(A, C_DIM, B, HR, m0, n0, c,
                           Asm + c * A_ST, Bsm + c * B_ST, tid);
                asm volatile("cp.async.commit_group;");
            }

            float acc[2][8][4];
#pragma unroll
            for (int i = 0; i < 2; i++)
#pragma unroll
                for (int j = 0; j < 8; j++)
#pragma unroll
                    for (int ee = 0; ee < 4; ee++) acc[i][j][ee] = 0.f;

            int s = 0, fs = NSTG - 1;
            for (int kt = 0; kt < KT; ++kt) {
                asm volatile("cp.async.wait_group %0;" :: "n"(NSTG - 2));
                __syncthreads();

                compute_stage(Asm + s * A_ST, Bsm + s * B_ST, acc, wm, wn, lane);

                if (kt + NSTG - 1 < KT)
                    fill_stage(A, C_DIM, B, HR, m0, n0, kt + NSTG - 1,
                               Asm + fs * A_ST, Bsm + fs * B_ST, tid);
                asm volatile("cp.async.commit_group;");

                if (++s == NSTG) s = 0;
                if (++fs == NSTG) fs = 0;
            }

#pragma unroll
            for (int mi = 0; mi < 2; mi++)
#pragma unroll
                for (int ni = 0; ni < 8; ni++)
#pragma unroll
                    for (int pp = 0; pp < 2; pp++) {
                        int row = m0 + wm * 32 + mi * 16 + (lane >> 2) + pp * 8;
                        int col = n0 + wn * 64 + ni * 8 + (lane & 3) * 2;
                        float v0 = acc[mi][ni][2 * pp + 0] + bias[col];
                        float v1 = acc[mi][ni][2 * pp + 1] + bias[col + 1];
                        v0 = 0.5f * v0 * (1.f + erff(v0 * 0.70710678118654752f));
                        v1 = 0.5f * v1 * (1.f + erff(v1 * 0.70710678118654752f));
                        *(__half2*)(outp + (size_t)row * HR + col) = __floats2half2_rn(v0, v1);
                    }
        }

        signal_ready(rr, tid);
    } else {
        // ---------- down: out = 0.5*shared_down + 0.25*(y0+y1) ----------
        const int idx = bid - N_UP;
        const int rr = idx >> 8;              // ascending residues
        const int rem = idx & 255;
        const int m0 = (rem >> 3) * BM;
        const int n0 = (rem & 7) * BN;
        const int e0 = (3 * rr) & 7;
        const int e1 = (3 * rr + 7) & 7;
        const int wm = warp & 3, wn = warp >> 2;

        // wait until all producers for this residue have committed
        if (tid == 0) {
            while (atomicAdd(&g_ready[rr], 0) < READY_TARGET) __nanosleep(200);
        }
        __syncthreads();
        __threadfence();                     // acquire side

#pragma unroll
        for (int c = 0; c < NSTG - 1; c++) {
            fill_stage_mega(c, rr, e0, e1, m0, n0,
                            Asm + c * A_ST, Bsm + c * B_ST, tid);
            asm volatile("cp.async.commit_group;");
        }

        float acc[2][8][4];
#pragma unroll
        for (int i = 0; i < 2; i++)
#pragma unroll
            for (int j = 0; j < 8; j++)
#pragma unroll
                for (int e = 0; e < 4; e++) acc[i][j][e] = 0.f;

        int s = 0, fs = NSTG - 1;
        for (int kt = 0; kt < KT_MEGA; ++kt) {
            asm volatile("cp.async.wait_group %0;" :: "n"(NSTG - 2));
            __syncthreads();

            compute_stage(Asm + s * A_ST, Bsm + s * B_ST, acc, wm, wn, lane);

            if (kt + NSTG - 1 < KT_MEGA)
                fill_stage_mega(kt + NSTG - 1, rr, e0, e1, m0, n0,
                                Asm + fs * A_ST, Bsm + fs * B_ST, tid);
            asm volatile("cp.async.commit_group;");

            if (++s == NSTG) s = 0;
            if (++fs == NSTG) fs = 0;
        }

        // epilogue: single fp32 write, precomputed combined bias, un-permute rows
        const float* biasD = g_biasD + rr * C_DIM;
#pragma unroll
        for (int mi = 0; mi < 2; mi++)
#pragma unroll
            for (int ni = 0; ni < 8; ni++)
#pragma unroll
                for (int pp = 0; pp < 2; pp++) {
                    int rowl = m0 + wm * 32 + mi * 16 + (lane >> 2) + pp * 8;
                    int col  = n0 + wn * 64 + ni * 8 + (lane & 3) * 2;
                    float2 bb = *(const float2*)(biasD + col);
                    float2 f;
                    f.x = acc[mi][ni][2 * pp + 0] + bb.x;
                    f.y = acc[mi][ni][2 * pp + 1] + bb.y;
                    size_t t = (size_t)rr + 8 * (size_t)rowl;    // actual token
                    *(float2*)(dout + t * C_DIM + col) = f;
                }
    }
}

// ---------------- launch ----------------
extern "C" void kernel_launch(void* const* d_in, const int* in_sizes, int n_in,
                              void* d_out, int out_size) {
    const float* x   = (const float*)d_in[0];
    // d_in[1] = t_emb : unused by reference
    const float* sw1 = (const float*)d_in[2];
    const float* sb1 = (const float*)d_in[3];
    const float* sw3 = (const float*)d_in[4];
    const float* sb3 = (const float*)d_in[5];
    const float* sw2 = (const float*)d_in[6];
    const float* sb2 = (const float*)d_in[7];
    const float* w1  = (const float*)d_in[8];
    const float* b1  = (const float*)d_in[9];
    const float* w2  = (const float*)d_in[10];
    const float* b2  = (const float*)d_in[11];
    float* out = (float*)d_out;

    cudaFuncSetAttribute(k_fused, cudaFuncAttributeMaxDynamicSharedMemorySize, SMEM_BYTES);

    // one merged conversion launch (MLP x4) + bias/counter-reset kernel
    k_convall<<<CV_QUARTER / 256, 256>>>(x, sw1, sw3, sw2, w1, w2);
    k_bias<<<(NE * C_DIM + 255) / 256, 256>>>(sb2, b2);

    // fused up+down: residue-major producers signal counters, consumers spin-wait
    k_fused<<<N_TOTAL, 256, SMEM_BYTES>>>(sb1, sb3, b1, out);
}